// round 16
// baseline (speedup 1.0000x reference)
#include <cuda_runtime.h>
#include <cuda_fp16.h>
#include <stdint.h>

// ---------------------------------------------------------------------------
// Problem dims (fixed by the dataset)
// ---------------------------------------------------------------------------
#define M_TOTAL 8192   // B*S = 4*2048
#define E_DIM   1024
#define P_DIM   4096
#define NROWBLK (M_TOTAL / 128)   // 64 row-blocks

// Device scratch (__device__ globals = sanctioned scratch)
__device__ float  g_scores[(size_t)M_TOTAL * (size_t)P_DIM]; // 128 MB fp32 scores
__device__ __half g_attn[(size_t)M_TOTAL * (size_t)P_DIM];   // 64 MB fp16 unnormalized e
__device__ float  g_rinv[M_TOTAL];                           // per-row 1/sum
__device__ __half g_xh[(size_t)M_TOTAL * (size_t)E_DIM];     // 16 MB fp16(x)
__device__ __half g_kh[(size_t)P_DIM * (size_t)E_DIM];       // 8 MB fp16(K)
__device__ __half g_vth[(size_t)E_DIM * (size_t)P_DIM];      // 8 MB fp16(V^T)
__device__ int    g_ticket[NROWBLK];                         // softmax arrival count
__device__ int    g_flag[NROWBLK];                           // row-block ready flag

// ---------------------------------------------------------------------------
// Helpers
// ---------------------------------------------------------------------------
__device__ __forceinline__ uint32_t smem_u32(const void* p) {
    uint32_t a;
    asm("{ .reg .u64 t; cvta.to.shared.u64 t, %1; cvt.u32.u64 %0, t; }"
        : "=r"(a) : "l"(p));
    return a;
}

__device__ __forceinline__ void cp_async16(uint32_t dst, const void* src) {
    asm volatile("cp.async.cg.shared.global [%0], [%1], 16;"
                 :: "r"(dst), "l"(src) : "memory");
}
#define CP_ASYNC_COMMIT() asm volatile("cp.async.commit_group;" ::: "memory")
#define CP_ASYNC_WAIT_1() asm volatile("cp.async.wait_group 1;" ::: "memory")

__device__ __forceinline__ void ldsm_x4(uint32_t r[4], uint32_t addr) {
    asm volatile("ldmatrix.sync.aligned.m8n8.x4.shared.b16 {%0,%1,%2,%3}, [%4];"
                 : "=r"(r[0]), "=r"(r[1]), "=r"(r[2]), "=r"(r[3]) : "r"(addr));
}

__device__ __forceinline__ void mma_f16(float c[4], const uint32_t a[4], const uint32_t b[2]) {
    asm volatile(
        "mma.sync.aligned.m16n8k16.row.col.f32.f16.f16.f32 "
        "{%0,%1,%2,%3}, {%4,%5,%6,%7}, {%8,%9}, {%0,%1,%2,%3};"
        : "+f"(c[0]), "+f"(c[1]), "+f"(c[2]), "+f"(c[3])
        : "r"(a[0]), "r"(a[1]), "r"(a[2]), "r"(a[3]),
          "r"(b[0]), "r"(b[1]));
}

// ---------------------------------------------------------------------------
// Common GEMM tiling: CTA 128x128, KC=64 halves (128-byte rows), 256 thr
// (8 warps 2x4), warp tile 64x32, mma m16n8k16, 3-stage cp.async, 2 CTAs/SM.
// XOR swizzle over 16B groups: byte(r,g) -> r*128 + ((g^(r&7))<<4).
// cp.async stores and all ldmatrix phases are bank-conflict-free.
// ---------------------------------------------------------------------------
#define BM 128
#define BN 128
#define KC64 64
#define STAGES 3
#define STG_WORDS 8192                        // 32KB per stage
#define SMEM_BYTES (STAGES * STG_WORDS * 4)   // 98304 per CTA

// The shared GEMM mainloop body is duplicated in the two kernels below
// (qk: plain epilogue to fp32 scores; av: softmax prologue + inv epilogue).

// ---------------------------------------------------------------------------
// QK GEMM: scores[m,p] = sum_e x[m,e]*K[p,e]  (raw; scale applied in softmax)
// ---------------------------------------------------------------------------
__global__ __launch_bounds__(256, 2) void gemm_qk(const __half* __restrict__ Ag,
                                                  const __half* __restrict__ Bg,
                                                  float* __restrict__ Dg) {
    extern __shared__ uint32_t sm[];
    const uint32_t sbase = smem_u32(sm);
    const int tid  = threadIdx.x;
    const int lane = tid & 31;
    const int wid  = tid >> 5;
    const int wm   = (wid >> 2) * 64;
    const int wn   = (wid & 3) * 32;
    const int bm   = blockIdx.y * BM;
    const int bn   = blockIdx.x * BN;
    const int tig  = lane & 3;
    const int grp  = lane >> 2;
    const int nk   = E_DIM / KC64;
    const int lda  = E_DIM, ldb = E_DIM, ldd = P_DIM;

    const int gflA = lane >> 4;
    uint32_t preA[4]; int rb7A[4];
    #pragma unroll
    for (int mi = 0; mi < 4; mi++) {
        int r = wm + mi * 16 + (lane & 15);
        preA[mi] = (uint32_t)(r * 128);
        rb7A[mi] = r & 7;
    }
    const int gflB = (lane >> 3) & 1;
    uint32_t preB[2]; int rb7B[2];
    #pragma unroll
    for (int np = 0; np < 2; np++) {
        int r = wn + np * 16 + ((lane >> 4) << 3) + (lane & 7);
        preB[np] = (uint32_t)(r * 128);
        rb7B[np] = r & 7;
    }

    auto issue_stage = [&](int stage, int k0) {
        const uint32_t abase = sbase + (uint32_t)stage * (STG_WORDS * 4);
        const uint32_t bbase = abase + 4096 * 4;
        #pragma unroll
        for (int i = 0; i < 4; i++) {
            int lin = tid + 256 * i;
            int r   = lin >> 3;
            int g   = lin & 7;
            uint32_t boff = (uint32_t)(r * 128 + ((g ^ (r & 7)) << 4));
            cp_async16(abase + boff, Ag + (size_t)(bm + r) * lda + k0 + g * 8);
        }
        #pragma unroll
        for (int i = 0; i < 4; i++) {
            int lin = tid + 256 * i;
            int r   = lin >> 3;
            int g   = lin & 7;
            uint32_t boff = (uint32_t)(r * 128 + ((g ^ (r & 7)) << 4));
            cp_async16(bbase + boff, Bg + (size_t)(bn + r) * ldb + k0 + g * 8);
        }
    };

    float acc[4][4][4];
    #pragma unroll
    for (int mi = 0; mi < 4; mi++)
        #pragma unroll
        for (int ni = 0; ni < 4; ni++)
            #pragma unroll
            for (int c = 0; c < 4; c++)
                acc[mi][ni][c] = 0.0f;

    issue_stage(0, 0);
    CP_ASYNC_COMMIT();
    issue_stage(1, KC64);
    CP_ASYNC_COMMIT();

    int stage_rd = 0, stage_wr = 2;
    for (int k = 0; k < nk; k++) {
        CP_ASYNC_WAIT_1();
        __syncthreads();
        const uint32_t astage = sbase + (uint32_t)stage_rd * (STG_WORDS * 4);
        const uint32_t bstage = astage + 4096 * 4;
        #pragma unroll
        for (int kk = 0; kk < 4; kk++) {
            uint32_t a[4][4];
            #pragma unroll
            for (int mi = 0; mi < 4; mi++) {
                uint32_t addr = astage + preA[mi] +
                                (uint32_t)((((2 * kk + gflA) ^ rb7A[mi])) << 4);
                ldsm_x4(a[mi], addr);
            }
            uint32_t b[4][2];
            {
                uint32_t b4[4];
                uint32_t addr0 = bstage + preB[0] +
                                 (uint32_t)((((2 * kk + gflB) ^ rb7B[0])) << 4);
                ldsm_x4(b4, addr0);
                b[0][0] = b4[0]; b[0][1] = b4[1];
                b[1][0] = b4[2]; b[1][1] = b4[3];
            }
            #pragma unroll
            for (int mi = 0; mi < 4; mi++) {
                mma_f16(acc[mi][0], a[mi], b[0]);
                mma_f16(acc[mi][1], a[mi], b[1]);
            }
            {
                uint32_t b4[4];
                uint32_t addr1 = bstage + preB[1] +
                                 (uint32_t)((((2 * kk + gflB) ^ rb7B[1])) << 4);
                ldsm_x4(b4, addr1);
                b[2][0] = b4[0]; b[2][1] = b4[1];
                b[3][0] = b4[2]; b[3][1] = b4[3];
            }
            #pragma unroll
            for (int mi = 0; mi < 4; mi++) {
                mma_f16(acc[mi][2], a[mi], b[2]);
                mma_f16(acc[mi][3], a[mi], b[3]);
            }
            if (kk == 0) {
                if (k + STAGES - 1 < nk)
                    issue_stage(stage_wr, (k + STAGES - 1) * KC64);
                CP_ASYNC_COMMIT();
            }
        }
        stage_rd = (stage_rd + 1 == STAGES) ? 0 : stage_rd + 1;
        stage_wr = (stage_wr + 1 == STAGES) ? 0 : stage_wr + 1;
    }

    #pragma unroll
    for (int mi = 0; mi < 4; mi++) {
        #pragma unroll
        for (int ni = 0; ni < 4; ni++) {
            const int r = bm + wm + mi * 16 + grp;
            const int c = bn + wn + ni * 8 + 2 * tig;
            float2 v0 = make_float2(acc[mi][ni][0], acc[mi][ni][1]);
            float2 v1 = make_float2(acc[mi][ni][2], acc[mi][ni][3]);
            *(float2*)&Dg[(size_t)r       * ldd + c] = v0;
            *(float2*)&Dg[(size_t)(r + 8) * ldd + c] = v1;
        }
    }
}

// ---------------------------------------------------------------------------
// Reset kernel: zero tickets/flags (must run each graph replay, before av).
// ---------------------------------------------------------------------------
__global__ void reset_sync() {
    int i = threadIdx.x;
    if (i < NROWBLK) { g_ticket[i] = 0; g_flag[i] = 0; }
}

// ---------------------------------------------------------------------------
// AV kernel with fused softmax prologue.
// Grid (E/128=8, M/128=64), x-fast -> the 8 siblings of a row-block are
// consecutive (304 slots = 38 full sibling groups per wave -> co-resident).
// Each sibling computes softmax for 16 of the 128 rows (warp-per-row, two
// passes; pass 2 is L2-hot), writes unnormalized e (fp16) + 1/sum, arrives
// on the ticket; 8th arrival sets the flag; everyone spins, then runs the
// standard fp16 GEMM over attn rows, scaling by inv[row] in the epilogue.
// ---------------------------------------------------------------------------
__global__ __launch_bounds__(256, 2) void gemm_av(float* __restrict__ Dg) {
    extern __shared__ uint32_t sm[];
    const uint32_t sbase = smem_u32(sm);
    const int tid  = threadIdx.x;
    const int lane = tid & 31;
    const int wid  = tid >> 5;
    const int wm   = (wid >> 2) * 64;
    const int wn   = (wid & 3) * 32;
    const int blkm = blockIdx.y;          // row-block index
    const int bm   = blkm * BM;
    const int bn   = blockIdx.x * BN;     // E column block
    const int tig  = lane & 3;
    const int grp  = lane >> 2;
    const int nk   = P_DIM / KC64;
    const int lda  = P_DIM, ldb = P_DIM, ldd = E_DIM;
    const float scale = 0.03125f;

    // ---- softmax share: rows bm + blockIdx.x*16 .. +16, warp-per-row ------
    {
        const int r0 = bm + blockIdx.x * 16;
        #pragma unroll
        for (int rr = 0; rr < 2; rr++) {
            const int row = r0 + wid * 2 + rr;
            const float4* srow = (const float4*)(g_scores + (size_t)row * P_DIM);
            // pass 1: max
            float m = -3.0e38f;
            #pragma unroll 8
            for (int i = 0; i < 32; i++) {
                float4 v = srow[lane + 32 * i];
                m = fmaxf(m, fmaxf(fmaxf(v.x, v.y), fmaxf(v.z, v.w)));
            }
            #pragma unroll
            for (int o = 16; o > 0; o >>= 1)
                m = fmaxf(m, __shfl_xor_sync(0xffffffffu, m, o));
            // pass 2: exp, sum, write fp16 e (L2-hot reload)
            uint2* arow = (uint2*)(g_attn + (size_t)row * P_DIM);
            float s = 0.0f;
            #pragma unroll 8
            for (int i = 0; i < 32; i++) {
                float4 v = srow[lane + 32 * i];
                float e0 = __expf((v.x - m) * scale);
                float e1 = __expf((v.y - m) * scale);
                float e2 = __expf((v.z - m) * scale);
                float e3 = __expf((v.w - m) * scale);
                s += e0 + e1 + e2 + e3;
                __half2 lo = __floats2half2_rn(e0, e1);
                __half2 hi = __floats2half2_rn(e2, e3);
                uint2 o;
                o.x = *(uint32_t*)&lo;
                o.y = *(uint32_t*)&hi;
                arow[lane + 32 * i] = o;
            }
            #pragma unroll
            for (int o = 16; o > 0; o >>= 1)
                s += __shfl_xor_sync(0xffffffffu, s, o);
            if (lane == 0) g_rinv[row] = 1.0f / s;
        }
    }
    __syncthreads();
    // ---- ticket + flag ----------------------------------------------------
    if (tid == 0) {
        __threadfence();                               // e + rinv visible
        int t = atomicAdd(&g_ticket[blkm], 1);
        if (t == 7) atomicExch(&g_flag[blkm], 1);      // last sibling: ready
        while (atomicAdd(&g_flag[blkm], 0) == 0) __nanosleep(64);
        __threadfence();                               // acquire
    }
    __syncthreads();

    // ---- standard fp16 GEMM over attn (A) and V^T (B) ---------------------
    const __half* Ag = g_attn;
    const __half* Bg = g_vth;

    const int gflA = lane >> 4;
    uint32_t preA[4]; int rb7A[4];
    #pragma unroll
    for (int mi = 0; mi < 4; mi++) {
        int r = wm + mi * 16 + (lane & 15);
        preA[mi] = (uint32_t)(r * 128);
        rb7A[mi] = r & 7;
    }
    const int gflB = (lane >> 3) & 1;
    uint32_t preB[2]; int rb7B[2];
    #pragma unroll
    for (int np = 0; np < 2; np++) {
        int r = wn + np * 16 + ((lane >> 4) << 3) + (lane & 7);
        preB[np] = (uint32_t)(r * 128);
        rb7B[np] = r & 7;
    }

    auto issue_stage = [&](int stage, int k0) {
        const uint32_t abase = sbase + (uint32_t)stage * (STG_WORDS * 4);
        const uint32_t bbase = abase + 4096 * 4;
        #pragma unroll
        for (int i = 0; i < 4; i++) {
            int lin = tid + 256 * i;
            int r   = lin >> 3;
            int g   = lin & 7;
            uint32_t boff = (uint32_t)(r * 128 + ((g ^ (r & 7)) << 4));
            cp_async16(abase + boff, Ag + (size_t)(bm + r) * lda + k0 + g * 8);
        }
        #pragma unroll
        for (int i = 0; i < 4; i++) {
            int lin = tid + 256 * i;
            int r   = lin >> 3;
            int g   = lin & 7;
            uint32_t boff = (uint32_t)(r * 128 + ((g ^ (r & 7)) << 4));
            cp_async16(bbase + boff, Bg + (size_t)(bn + r) * ldb + k0 + g * 8);
        }
    };

    float acc[4][4][4];
    #pragma unroll
    for (int mi = 0; mi < 4; mi++)
        #pragma unroll
        for (int ni = 0; ni < 4; ni++)
            #pragma unroll
            for (int c = 0; c < 4; c++)
                acc[mi][ni][c] = 0.0f;

    issue_stage(0, 0);
    CP_ASYNC_COMMIT();
    issue_stage(1, KC64);
    CP_ASYNC_COMMIT();

    int stage_rd = 0, stage_wr = 2;
    for (int k = 0; k < nk; k++) {
        CP_ASYNC_WAIT_1();
        __syncthreads();
        const uint32_t astage = sbase + (uint32_t)stage_rd * (STG_WORDS * 4);
        const uint32_t bstage = astage + 4096 * 4;
        #pragma unroll
        for (int kk = 0; kk < 4; kk++) {
            uint32_t a[4][4];
            #pragma unroll
            for (int mi = 0; mi < 4; mi++) {
                uint32_t addr = astage + preA[mi] +
                                (uint32_t)((((2 * kk + gflA) ^ rb7A[mi])) << 4);
                ldsm_x4(a[mi], addr);
            }
            uint32_t b[4][2];
            {
                uint32_t b4[4];
                uint32_t addr0 = bstage + preB[0] +
                                 (uint32_t)((((2 * kk + gflB) ^ rb7B[0])) << 4);
                ldsm_x4(b4, addr0);
                b[0][0] = b4[0]; b[0][1] = b4[1];
                b[1][0] = b4[2]; b[1][1] = b4[3];
            }
            #pragma unroll
            for (int mi = 0; mi < 4; mi++) {
                mma_f16(acc[mi][0], a[mi], b[0]);
                mma_f16(acc[mi][1], a[mi], b[1]);
            }
            {
                uint32_t b4[4];
                uint32_t addr1 = bstage + preB[1] +
                                 (uint32_t)((((2 * kk + gflB) ^ rb7B[1])) << 4);
                ldsm_x4(b4, addr1);
                b[2][0] = b4[0]; b[2][1] = b4[1];
                b[3][0] = b4[2]; b[3][1] = b4[3];
            }
            #pragma unroll
            for (int mi = 0; mi < 4; mi++) {
                mma_f16(acc[mi][2], a[mi], b[2]);
                mma_f16(acc[mi][3], a[mi], b[3]);
            }
            if (kk == 0) {
                if (k + STAGES - 1 < nk)
                    issue_stage(stage_wr, (k + STAGES - 1) * KC64);
                CP_ASYNC_COMMIT();
            }
        }
        stage_rd = (stage_rd + 1 == STAGES) ? 0 : stage_rd + 1;
        stage_wr = (stage_wr + 1 == STAGES) ? 0 : stage_wr + 1;
    }

    // Epilogue: scale by per-row 1/sum, store fp32.
    #pragma unroll
    for (int mi = 0; mi < 4; mi++) {
        const int r = bm + wm + mi * 16 + grp;
        const float inv0 = g_rinv[r];
        const float inv1 = g_rinv[r + 8];
        #pragma unroll
        for (int ni = 0; ni < 4; ni++) {
            const int c = bn + wn + ni * 8 + 2 * tig;
            float2 v0 = make_float2(acc[mi][ni][0] * inv0, acc[mi][ni][1] * inv0);
            float2 v1 = make_float2(acc[mi][ni][2] * inv1, acc[mi][ni][3] * inv1);
            *(float2*)&Dg[(size_t)r       * ldd + c] = v0;
            *(float2*)&Dg[(size_t)(r + 8) * ldd + c] = v1;
        }
    }
}

// ---------------------------------------------------------------------------
// Elementwise fp16 convert for x and K in ONE launch (8 floats/thread).
// ---------------------------------------------------------------------------
#define NX ((size_t)M_TOTAL * E_DIM)
#define NK ((size_t)P_DIM * E_DIM)
__global__ __launch_bounds__(256) void cvt_inputs(const float* __restrict__ x,
                                                  const float* __restrict__ Kw,
                                                  __half* __restrict__ xh,
                                                  __half* __restrict__ kh) {
    const size_t i = ((size_t)blockIdx.x * 256 + threadIdx.x) * 8;
    const float* src;
    __half* dst;
    size_t off;
    if (i < NX) { src = x;  dst = xh; off = i; }
    else        { src = Kw; dst = kh; off = i - NX; }
    float4 v0 = *(const float4*)(src + off);
    float4 v1 = *(const float4*)(src + off + 4);
    __half2 h0 = __floats2half2_rn(v0.x, v0.y);
    __half2 h1 = __floats2half2_rn(v0.z, v0.w);
    __half2 h2 = __floats2half2_rn(v1.x, v1.y);
    __half2 h3 = __floats2half2_rn(v1.z, v1.w);
    uint4 w;
    w.x = *(uint32_t*)&h0; w.y = *(uint32_t*)&h1;
    w.z = *(uint32_t*)&h2; w.w = *(uint32_t*)&h3;
    *(uint4*)(dst + off) = w;
}

// ---------------------------------------------------------------------------
// V transpose + fp16 convert: g_vth[e][p] = fp16(V[p][e])
// ---------------------------------------------------------------------------
__global__ __launch_bounds__(256) void transpose_v(const float* __restrict__ V) {
    __shared__ float t[32][33];
    const int bx = blockIdx.x * 32;  // E
    const int by = blockIdx.y * 32;  // P
    const int tx = threadIdx.x;
    const int ty = threadIdx.y;
    #pragma unroll
    for (int j = 0; j < 32; j += 8)
        t[ty + j][tx] = V[(size_t)(by + ty + j) * E_DIM + bx + tx];
    __syncthreads();
    #pragma unroll
    for (int j = 0; j < 32; j += 8)
        g_vth[(size_t)(bx + ty + j) * P_DIM + by + tx] =
            __float2half_rn(t[tx][ty + j]);
}

// ---------------------------------------------------------------------------
// Launch. Inputs: x [4,2048,1024], K [4096,1024], V [4096,1024]; out fp32.
// Only kernel launches enqueued -> graph-capturable.
// ---------------------------------------------------------------------------
extern "C" void kernel_launch(void* const* d_in, const int* in_sizes, int n_in,
                              void* d_out, int out_size) {
    (void)in_sizes; (void)n_in; (void)out_size;
    const float* x  = (const float*)d_in[0];
    const float* Kw = (const float*)d_in[1];
    const float* V  = (const float*)d_in[2];
    float* out = (float*)d_out;

    cudaFuncSetAttribute(gemm_qk, cudaFuncAttributeMaxDynamicSharedMemorySize,
                         SMEM_BYTES);
    cudaFuncSetAttribute(gemm_av, cudaFuncAttributeMaxDynamicSharedMemorySize,
                         SMEM_BYTES);

    void *p_scores, *p_xh, *p_kh;
    cudaGetSymbolAddress(&p_scores, g_scores);
    cudaGetSymbolAddress(&p_xh, g_xh);
    cudaGetSymbolAddress(&p_kh, g_kh);
    float* scores = (float*)p_scores;
    __half* xh = (__half*)p_xh;
    __half* kh = (__half*)p_kh;

    // Reset softmax tickets/flags (fresh each graph replay).
    reset_sync<<<1, 64>>>();

    // Pre-convert x,K to fp16 (one fused launch); transpose+fp16-convert V.
    cvt_inputs<<<(unsigned)((NX + NK) / 2048), 256>>>(x, Kw, xh, kh);
    transpose_v<<<dim3(E_DIM / 32, P_DIM / 32), dim3(32, 8)>>>(V);

    // raw scores = x @ K^T (fp16 in, fp32 accum)
    gemm_qk<<<dim3(P_DIM / BN, M_TOTAL / BM), 256, SMEM_BYTES>>>(xh, kh, scores);

    // out = softmax(scores/32) @ V, softmax fused into the AV kernel.
    gemm_av<<<dim3(E_DIM / BN, M_TOTAL / BM), 256, SMEM_BYTES>>>(out);
}